// round 1
// baseline (speedup 1.0000x reference)
#include <cuda_runtime.h>
#include <math.h>

#define Bn 512
#define Ln 64
#define En 256
#define Hn 256
#define CD 64
#define HCn 320     // H + CDIM
#define KX 512      // E + H
#define G4 1024     // 4*H
#define NEGV -1000000000.0f

// ---------------- scratch (static device globals; allocation-free) ----------
__device__ float g_eg[Bn*Ln*Hn];     // e_g  [b][l][h]
__device__ float g_ep[Bn*Ln*Hn];     // e_p  [b][l][h]
__device__ float g_xh[Bn*KX];        // [x | h] LSTM input
__device__ float g_hc[Bn*HCn];       // [h | courier]
__device__ float g_gates[Bn*G4];
__device__ float g_c[Bn*Hn];
__device__ float g_gl[Bn*Hn];
__device__ float g_qg[Bn*Hn];
__device__ float g_gl2[Bn*Hn];
__device__ float g_qp[Bn*Hn];
__device__ float g_Wcat[G4*KX];      // [W_ih | W_hh]
__device__ float g_bcat[G4];         // b_ih + b_hh
__device__ unsigned char g_mask[Bn*Ln];

__device__ __forceinline__ float sigf(float x) { return 1.0f/(1.0f+expf(-x)); }

// ---------------- generic tiled fp32 GEMM: C = A @ W^T + bias ---------------
// C[m][n] = sum_k A[row(m)][k] * W[n][k] + bias[n]
// REMAP=1: row(m) = (m%64)*Bn + m/64   (context (L,B,H) -> rows ordered (b,l))
template<int REMAP>
__global__ __launch_bounds__(256) void gemm_bias(
    const float* __restrict__ A, const float* __restrict__ W,
    const float* __restrict__ bias, float* __restrict__ C,
    int M, int N, int K)
{
    __shared__ float As[16][64];
    __shared__ float Ws[16][64];
    const int m0 = blockIdx.y * 64, n0 = blockIdx.x * 64;
    const int tid = threadIdx.x;
    const int lr = tid >> 2;          // 0..63
    const int lc = (tid & 3) * 4;     // 0,4,8,12
    const int ty = tid >> 4, tx = tid & 15;

    float acc[4][4] = {};
    int mrow = m0 + lr;
    int arow = REMAP ? ((mrow & 63) * Bn + (mrow >> 6)) : mrow;
    const float* Ap = A + (size_t)arow * K + lc;
    const float* Wp = W + (size_t)(n0 + lr) * K + lc;

    for (int k0 = 0; k0 < K; k0 += 16) {
        float4 av = *(const float4*)(Ap + k0);
        float4 wv = *(const float4*)(Wp + k0);
        As[lc+0][lr]=av.x; As[lc+1][lr]=av.y; As[lc+2][lr]=av.z; As[lc+3][lr]=av.w;
        Ws[lc+0][lr]=wv.x; Ws[lc+1][lr]=wv.y; Ws[lc+2][lr]=wv.z; Ws[lc+3][lr]=wv.w;
        __syncthreads();
        #pragma unroll
        for (int kk = 0; kk < 16; kk++) {
            float4 a = *(const float4*)&As[kk][ty*4];
            float4 w = *(const float4*)&Ws[kk][tx*4];
            float ar[4] = {a.x,a.y,a.z,a.w};
            float wr[4] = {w.x,w.y,w.z,w.w};
            #pragma unroll
            for (int i = 0; i < 4; i++)
                #pragma unroll
                for (int j = 0; j < 4; j++)
                    acc[i][j] += ar[i]*wr[j];
        }
        __syncthreads();
    }
    #pragma unroll
    for (int i = 0; i < 4; i++) {
        int m = m0 + ty*4 + i;
        float* Crow = C + (size_t)m*N + n0 + tx*4;
        #pragma unroll
        for (int j = 0; j < 4; j++)
            Crow[j] = acc[i][j] + bias[n0 + tx*4 + j];
    }
}

// ---------------- one-time setup ----------------
__global__ void setup_kernel(
    const float* __restrict__ dec, const float* __restrict__ h0,
    const float* __restrict__ c0, const float* __restrict__ courier,
    const unsigned char* __restrict__ im,
    const float* __restrict__ W_ih, const float* __restrict__ W_hh,
    const float* __restrict__ b_ih, const float* __restrict__ b_hh)
{
    int i = blockIdx.x * blockDim.x + threadIdx.x;
    if (i < G4*KX) {
        int n = i / KX, k = i % KX;
        g_Wcat[i] = (k < En) ? W_ih[n*En + k] : W_hh[n*Hn + (k - En)];
    }
    if (i < G4)    g_bcat[i] = b_ih[i] + b_hh[i];
    if (i < Bn*KX) {
        int b = i / KX, j = i % KX;
        g_xh[i] = (j < En) ? dec[b*En + j] : h0[b*Hn + (j - En)];
    }
    if (i < Bn*Hn) g_c[i] = c0[i];
    if (i < Bn*CD) {
        int b = i / CD, j = i % CD;
        g_hc[b*HCn + Hn + j] = courier[i];
    }
    if (i < Bn*Ln) g_mask[i] = im[i];
}

// ---------------- LSTM pointwise epilogue ----------------
__global__ __launch_bounds__(256) void lstm_epi() {
    int b = blockIdx.x, j = threadIdx.x;
    const float* g = g_gates + b*G4;
    float iv = sigf(g[j]);
    float fv = sigf(g[j + 256]);
    float gv = tanhf(g[j + 512]);
    float ov = sigf(g[j + 768]);
    float c = fv * g_c[b*Hn + j] + iv * gv;
    float h = ov * tanhf(c);
    g_c[b*Hn + j]       = c;
    g_xh[b*KX + En + j] = h;
    g_hc[b*HCn + j]     = h;
}

// ---------------- attention g: scores + softmax + weighted sum (fused) ------
__global__ __launch_bounds__(256) void attn_g_kernel(const float* __restrict__ vg) {
    extern __shared__ float es[];               // 64*256 floats (64 KB)
    __shared__ float qs[256], vs[256], wv[64];
    int b = blockIdx.x, t = threadIdx.x;

    const float4* src = (const float4*)(g_eg + (size_t)b * Ln * Hn);
    float4* d4 = (float4*)es;
    #pragma unroll
    for (int i = t; i < 4096; i += 256) d4[i] = src[i];
    qs[t] = g_qg[b*Hn + t];
    vs[t] = vg[t];
    __syncthreads();

    int warp = t >> 5, lane = t & 31;
    #pragma unroll
    for (int l0 = 0; l0 < 64; l0 += 8) {
        int l = l0 + warp;
        const float* row = es + l * 256;
        float acc = 0.f;
        #pragma unroll
        for (int j = 0; j < 8; j++) {
            int h = lane + 32*j;
            acc += vs[h] * tanhf(qs[h] + row[h]);
        }
        #pragma unroll
        for (int o = 16; o; o >>= 1) acc += __shfl_xor_sync(0xffffffffu, acc, o);
        if (lane == 0) wv[l] = g_mask[b*Ln + l] ? NEGV : acc;
    }
    __syncthreads();

    if (warp == 0) {
        float a = wv[lane], c = wv[lane + 32];
        float m = fmaxf(a, c);
        #pragma unroll
        for (int o = 16; o; o >>= 1) m = fmaxf(m, __shfl_xor_sync(0xffffffffu, m, o));
        float ea = expf(a - m), ec = expf(c - m);
        float s = ea + ec;
        #pragma unroll
        for (int o = 16; o; o >>= 1) s += __shfl_xor_sync(0xffffffffu, s, o);
        wv[lane]      = ea / s;
        wv[lane + 32] = ec / s;
    }
    __syncthreads();

    float acc = 0.f;
    #pragma unroll
    for (int l = 0; l < 64; l++) acc += es[l*256 + t] * wv[l];
    g_gl2[b*Hn + t] = acc;
}

// ---------------- attention p: log-softmax + argmax + mask + gather ---------
__global__ __launch_bounds__(256) void attn_p_kernel(
    const float* __restrict__ vp, const float* __restrict__ emb,
    float* __restrict__ out, int step)
{
    extern __shared__ float es[];               // 64*256 floats
    __shared__ float qs[256], vs[256], wv[64];
    __shared__ float s_m, s_ls;
    __shared__ int   s_sel;
    int b = blockIdx.x, t = threadIdx.x;

    const float4* src = (const float4*)(g_ep + (size_t)b * Ln * Hn);
    float4* d4 = (float4*)es;
    #pragma unroll
    for (int i = t; i < 4096; i += 256) d4[i] = src[i];
    qs[t] = g_qp[b*Hn + t];
    vs[t] = vp[t];
    __syncthreads();

    int warp = t >> 5, lane = t & 31;
    #pragma unroll
    for (int l0 = 0; l0 < 64; l0 += 8) {
        int l = l0 + warp;
        const float* row = es + l * 256;
        float acc = 0.f;
        #pragma unroll
        for (int j = 0; j < 8; j++) {
            int h = lane + 32*j;
            acc += vs[h] * tanhf(qs[h] + row[h]);
        }
        #pragma unroll
        for (int o = 16; o; o >>= 1) acc += __shfl_xor_sync(0xffffffffu, acc, o);
        if (lane == 0) wv[l] = g_mask[b*Ln + l] ? NEGV : (10.0f * tanhf(acc));
    }
    __syncthreads();

    if (warp == 0) {
        float a = wv[lane], c = wv[lane + 32];
        float m = fmaxf(a, c);
        #pragma unroll
        for (int o = 16; o; o >>= 1) m = fmaxf(m, __shfl_xor_sync(0xffffffffu, m, o));
        float s = expf(a - m) + expf(c - m);
        #pragma unroll
        for (int o = 16; o; o >>= 1) s += __shfl_xor_sync(0xffffffffu, s, o);
        // argmax with first-index tie-break (matches jnp.argmax)
        float bv = a; int bi = lane;
        if (c > bv) { bv = c; bi = lane + 32; }
        #pragma unroll
        for (int o = 16; o; o >>= 1) {
            float ov = __shfl_xor_sync(0xffffffffu, bv, o);
            int   oi = __shfl_xor_sync(0xffffffffu, bi, o);
            if (ov > bv || (ov == bv && oi < bi)) { bv = ov; bi = oi; }
        }
        if (lane == 0) {
            s_m = m; s_ls = logf(s); s_sel = bi;
            unsigned char* mk = g_mask + b*Ln;
            mk[bi] = 1;
            int cnt = 0;
            #pragma unroll
            for (int l = 0; l < Ln; l++) cnt += mk[l];
            if (cnt == Ln) mk[Ln - 1] = 0;     // update_mask: reset last col if all true
            out[(size_t)(Bn*Ln*Ln) + (size_t)b*Ln + step] = (float)bi;  // sels
        }
    }
    __syncthreads();

    if (t < Ln)
        out[(size_t)b*Ln*Ln + (size_t)step*Ln + t] = wv[t] - s_m - s_ls;  // log_p

    int sel = s_sel;                            // gather next x
    g_xh[b*KX + t] = emb[((size_t)sel*Bn + b)*En + t];
}

// ---------------- host ----------------
extern "C" void kernel_launch(void* const* d_in, const int* in_sizes, int n_in,
                              void* d_out, int out_size)
{
    const float* dec     = (const float*)d_in[0];
    const float* emb     = (const float*)d_in[1];
    const float* h0      = (const float*)d_in[2];
    const float* c0      = (const float*)d_in[3];
    const float* ctx     = (const float*)d_in[4];
    const float* courier = (const float*)d_in[5];
    const unsigned char* initm = (const unsigned char*)d_in[6];
    const float* W_ih = (const float*)d_in[7];
    const float* W_hh = (const float*)d_in[8];
    const float* b_ih = (const float*)d_in[9];
    const float* b_hh = (const float*)d_in[10];
    const float* Wm   = (const float*)d_in[11];
    const float* bm   = (const float*)d_in[12];
    const float* Wq_p = (const float*)d_in[13];
    const float* bq_p = (const float*)d_in[14];
    const float* Wr_p = (const float*)d_in[15];
    const float* br_p = (const float*)d_in[16];
    const float* v_p  = (const float*)d_in[17];
    const float* Wq_g = (const float*)d_in[18];
    const float* bq_g = (const float*)d_in[19];
    const float* Wr_g = (const float*)d_in[20];
    const float* br_g = (const float*)d_in[21];
    const float* v_g  = (const float*)d_in[22];
    float* out = (float*)d_out;

    cudaFuncSetAttribute(attn_g_kernel, cudaFuncAttributeMaxDynamicSharedMemorySize, 65536);
    cudaFuncSetAttribute(attn_p_kernel, cudaFuncAttributeMaxDynamicSharedMemorySize, 65536);

    float *eg, *ep, *xh, *hc, *gates, *gl, *qg, *gl2, *qp, *Wcat, *bcat;
    cudaGetSymbolAddress((void**)&eg,    g_eg);
    cudaGetSymbolAddress((void**)&ep,    g_ep);
    cudaGetSymbolAddress((void**)&xh,    g_xh);
    cudaGetSymbolAddress((void**)&hc,    g_hc);
    cudaGetSymbolAddress((void**)&gates, g_gates);
    cudaGetSymbolAddress((void**)&gl,    g_gl);
    cudaGetSymbolAddress((void**)&qg,    g_qg);
    cudaGetSymbolAddress((void**)&gl2,   g_gl2);
    cudaGetSymbolAddress((void**)&qp,    g_qp);
    cudaGetSymbolAddress((void**)&Wcat,  g_Wcat);
    cudaGetSymbolAddress((void**)&bcat,  g_bcat);

    setup_kernel<<<1024, 512>>>(dec, h0, c0, courier, initm, W_ih, W_hh, b_ih, b_hh);

    // e_g / e_p = context @ Wr^T + br, stored [b][l][h]
    gemm_bias<1><<<dim3(Hn/64, (Bn*Ln)/64), 256>>>(ctx, Wr_g, br_g, eg, Bn*Ln, Hn, Hn);
    gemm_bias<1><<<dim3(Hn/64, (Bn*Ln)/64), 256>>>(ctx, Wr_p, br_p, ep, Bn*Ln, Hn, Hn);

    for (int t = 0; t < Ln; t++) {
        gemm_bias<0><<<dim3(G4/64, Bn/64), 256>>>(xh, Wcat, bcat, gates, Bn, G4, KX);
        lstm_epi<<<Bn, Hn>>>();
        gemm_bias<0><<<dim3(Hn/64, Bn/64), 256>>>(hc,  Wm,   bm,   gl, Bn, Hn, HCn);
        gemm_bias<0><<<dim3(Hn/64, Bn/64), 256>>>(gl,  Wq_g, bq_g, qg, Bn, Hn, Hn);
        attn_g_kernel<<<Bn, 256, 65536>>>(v_g);
        gemm_bias<0><<<dim3(Hn/64, Bn/64), 256>>>(gl2, Wq_p, bq_p, qp, Bn, Hn, Hn);
        attn_p_kernel<<<Bn, 256, 65536>>>(v_p, emb, out, t);
    }
}

// round 2
// speedup vs baseline: 1.0871x; 1.0871x over previous
#include <cuda_runtime.h>
#include <math.h>

#define Bn 512
#define Ln 64
#define En 256
#define Hn 256
#define CD 64
#define HCn 320     // H + CDIM
#define KX 512      // E + H
#define G4 1024     // 4*H
#define NEGV -1000000000.0f
#define NBLK 296    // 2 blocks per SM on 148 SMs (152 on GB300 -> even safer)

// ---------------- scratch (static device globals; allocation-free) ----------
__device__ float g_eg[Bn*Ln*Hn];     // e_g  [b][l][h]
__device__ float g_ep[Bn*Ln*Hn];     // e_p  [b][l][h]
__device__ float g_xh[Bn*KX];        // [x | h] LSTM input
__device__ float g_hc[Bn*HCn];       // [h | courier]
__device__ float g_gates[Bn*G4];
__device__ float g_c[Bn*Hn];
__device__ float g_gl[Bn*Hn];
__device__ float g_qg[Bn*Hn];
__device__ float g_gl2[Bn*Hn];
__device__ float g_qp[Bn*Hn];
__device__ float g_Wcat[G4*KX];      // [W_ih | W_hh]
__device__ float g_bcat[G4];         // b_ih + b_hh
__device__ unsigned char g_mask[Bn*Ln];
__device__ unsigned int g_sync;      // grid barrier counter (reset each launch)

__device__ __forceinline__ float sigf(float x) { return 1.0f/(1.0f+expf(-x)); }

// ---------------- software grid barrier (all NBLK blocks resident) ----------
__device__ __forceinline__ void gbar(unsigned int &cnt) {
    __syncthreads();
    cnt += gridDim.x;
    if (threadIdx.x == 0) {
        __threadfence();                         // release (CCTL.IVALL on sm_103a)
        atomicAdd(&g_sync, 1u);
        while (*(volatile unsigned int*)&g_sync < cnt) { }
        __threadfence();                         // acquire
    }
    __syncthreads();
}

// ---------------- tiled GEMM phase: C = A @ W^T + bias ----------------------
// TM x 64 tile, 256 threads, double-buffered smem, K multiple of 16, lda == K.
template<int TM>
__device__ void gemm_phase(const float* __restrict__ A, const float* __restrict__ W,
                           const float* __restrict__ bias, float* __restrict__ C,
                           int M, int N, int K,
                           float (*sA)[16][32], float (*sW)[16][64])
{
    const int tid = threadIdx.x;
    const int tm = tid >> 4;           // 0..15
    const int tn = tid & 15;           // cols 4*tn..4*tn+3
    const int mt = M / TM, nt = N >> 6;
    const int njobs = mt * nt;
    const bool aAct = tid < TM * 4;
    const int am = tid >> 2;           // A row within tile
    const int ak = (tid & 3) << 2;     // k offset within 16-chunk
    const int wn = tid >> 2;           // W row within 64-tile
    const int wk = (tid & 3) << 2;

    for (int job = blockIdx.x; job < njobs; job += gridDim.x) {
        const int m0 = (job % mt) * TM;
        const int n0 = (job / mt) << 6;
        const float* Arow = A + (size_t)(m0 + am) * K + ak;
        const float* Wrow = W + (size_t)(n0 + wn) * K + wk;
        float4 ra, rw;
        if (aAct) ra = *(const float4*)(Arow);
        rw = *(const float4*)(Wrow);
        float acc0[4] = {0,0,0,0}, acc1[4] = {0,0,0,0};
        __syncthreads();                           // smem reuse across jobs/phases
        int buf = 0;
        for (int k0 = 0; k0 < K; k0 += 16) {
            if (aAct) {
                sA[buf][ak+0][am] = ra.x; sA[buf][ak+1][am] = ra.y;
                sA[buf][ak+2][am] = ra.z; sA[buf][ak+3][am] = ra.w;
            }
            sW[buf][wk+0][wn] = rw.x; sW[buf][wk+1][wn] = rw.y;
            sW[buf][wk+2][wn] = rw.z; sW[buf][wk+3][wn] = rw.w;
            __syncthreads();
            if (k0 + 16 < K) {                     // prefetch next chunk into regs
                if (aAct) ra = *(const float4*)(Arow + k0 + 16);
                rw = *(const float4*)(Wrow + k0 + 16);
            }
            #pragma unroll
            for (int kk = 0; kk < 16; kk++) {
                const float4 w = *(const float4*)&sW[buf][kk][tn << 2];
                const float a0 = sA[buf][kk][tm];
                acc0[0] = fmaf(a0, w.x, acc0[0]);
                acc0[1] = fmaf(a0, w.y, acc0[1]);
                acc0[2] = fmaf(a0, w.z, acc0[2]);
                acc0[3] = fmaf(a0, w.w, acc0[3]);
                if (TM == 32) {
                    const float a1 = sA[buf][kk][tm + 16];
                    acc1[0] = fmaf(a1, w.x, acc1[0]);
                    acc1[1] = fmaf(a1, w.y, acc1[1]);
                    acc1[2] = fmaf(a1, w.z, acc1[2]);
                    acc1[3] = fmaf(a1, w.w, acc1[3]);
                }
            }
            buf ^= 1;
        }
        const int nc = n0 + (tn << 2);
        float b0 = bias[nc+0], b1 = bias[nc+1], b2 = bias[nc+2], b3 = bias[nc+3];
        float* Cr = C + (size_t)(m0 + tm) * N + nc;
        Cr[0] = acc0[0] + b0; Cr[1] = acc0[1] + b1;
        Cr[2] = acc0[2] + b2; Cr[3] = acc0[3] + b3;
        if (TM == 32) {
            float* Cr2 = C + (size_t)(m0 + tm + 16) * N + nc;
            Cr2[0] = acc1[0] + b0; Cr2[1] = acc1[1] + b1;
            Cr2[2] = acc1[2] + b2; Cr2[3] = acc1[3] + b3;
        }
    }
}

// ---------------- one-time e_g/e_p GEMM (unchanged from R1) -----------------
template<int REMAP>
__global__ __launch_bounds__(256) void gemm_bias(
    const float* __restrict__ A, const float* __restrict__ W,
    const float* __restrict__ bias, float* __restrict__ C,
    int M, int N, int K)
{
    __shared__ float As[16][64];
    __shared__ float Ws[16][64];
    const int m0 = blockIdx.y * 64, n0 = blockIdx.x * 64;
    const int tid = threadIdx.x;
    const int lr = tid >> 2;
    const int lc = (tid & 3) * 4;
    const int ty = tid >> 4, tx = tid & 15;

    float acc[4][4] = {};
    int mrow = m0 + lr;
    int arow = REMAP ? ((mrow & 63) * Bn + (mrow >> 6)) : mrow;
    const float* Ap = A + (size_t)arow * K + lc;
    const float* Wp = W + (size_t)(n0 + lr) * K + lc;

    for (int k0 = 0; k0 < K; k0 += 16) {
        float4 av = *(const float4*)(Ap + k0);
        float4 wv = *(const float4*)(Wp + k0);
        As[lc+0][lr]=av.x; As[lc+1][lr]=av.y; As[lc+2][lr]=av.z; As[lc+3][lr]=av.w;
        Ws[lc+0][lr]=wv.x; Ws[lc+1][lr]=wv.y; Ws[lc+2][lr]=wv.z; Ws[lc+3][lr]=wv.w;
        __syncthreads();
        #pragma unroll
        for (int kk = 0; kk < 16; kk++) {
            float4 a = *(const float4*)&As[kk][ty*4];
            float4 w = *(const float4*)&Ws[kk][tx*4];
            float ar[4] = {a.x,a.y,a.z,a.w};
            float wr[4] = {w.x,w.y,w.z,w.w};
            #pragma unroll
            for (int i = 0; i < 4; i++)
                #pragma unroll
                for (int j = 0; j < 4; j++)
                    acc[i][j] += ar[i]*wr[j];
        }
        __syncthreads();
    }
    #pragma unroll
    for (int i = 0; i < 4; i++) {
        int m = m0 + ty*4 + i;
        float* Crow = C + (size_t)m*N + n0 + tx*4;
        #pragma unroll
        for (int j = 0; j < 4; j++)
            Crow[j] = acc[i][j] + bias[n0 + tx*4 + j];
    }
}

// ---------------- one-time setup ----------------
__global__ void setup_kernel(
    const float* __restrict__ dec, const float* __restrict__ h0,
    const float* __restrict__ c0, const float* __restrict__ courier,
    const unsigned char* __restrict__ im,
    const float* __restrict__ W_ih, const float* __restrict__ W_hh,
    const float* __restrict__ b_ih, const float* __restrict__ b_hh)
{
    int i = blockIdx.x * blockDim.x + threadIdx.x;
    if (i == 0) g_sync = 0;                       // reset grid barrier each launch
    if (i < G4*KX) {
        int n = i / KX, k = i % KX;
        g_Wcat[i] = (k < En) ? W_ih[n*En + k] : W_hh[n*Hn + (k - En)];
    }
    if (i < G4)    g_bcat[i] = b_ih[i] + b_hh[i];
    if (i < Bn*KX) {
        int b = i / KX, j = i % KX;
        g_xh[i] = (j < En) ? dec[b*En + j] : h0[b*Hn + (j - En)];
    }
    if (i < Bn*Hn) g_c[i] = c0[i];
    if (i < Bn*CD) {
        int b = i / CD, j = i % CD;
        g_hc[b*HCn + Hn + j] = courier[i];
    }
    if (i < Bn*Ln) g_mask[i] = im[i];
}

// ---------------- the persistent decoder kernel -----------------------------
__global__ __launch_bounds__(256, 2) void persist_kernel(
    const float* __restrict__ emb,
    const float* __restrict__ Wm,   const float* __restrict__ bm,
    const float* __restrict__ Wq_g, const float* __restrict__ bq_g,
    const float* __restrict__ Wq_p, const float* __restrict__ bq_p,
    const float* __restrict__ v_g,  const float* __restrict__ v_p,
    float* __restrict__ out)
{
    extern __shared__ float es[];                // 64 KB e-tile
    __shared__ float sA[2][16][32];
    __shared__ float sW[2][16][64];
    __shared__ float qs[256], vs[256], wv[64];
    __shared__ float s_m, s_ls;
    __shared__ int   s_sel;

    const int t = threadIdx.x;
    const int warp = t >> 5, lane = t & 31;
    const int nthr = gridDim.x * blockDim.x;
    unsigned int barcnt = 0;

    for (int step = 0; step < Ln; step++) {
        // ---- P1: gates = [x|h] @ Wcat^T + bcat  (M=512, N=1024, K=512) ----
        gemm_phase<32>(g_xh, g_Wcat, g_bcat, g_gates, Bn, G4, KX, sA, sW);
        gbar(barcnt);

        // ---- P2: LSTM pointwise ----
        for (int i = blockIdx.x * blockDim.x + t; i < Bn*Hn; i += nthr) {
            int b = i >> 8, j = i & 255;
            const float* g = g_gates + b*G4;
            float iv = sigf(g[j]);
            float fv = sigf(g[j + 256]);
            float gv = tanhf(g[j + 512]);
            float ov = sigf(g[j + 768]);
            float c = fv * g_c[i] + iv * gv;
            float h = ov * tanhf(c);
            g_c[i]              = c;
            g_xh[b*KX + En + j] = h;
            g_hc[b*HCn + j]     = h;
        }
        gbar(barcnt);

        // ---- P3: gl = [h|courier] @ Wm^T + bm  (K=320) ----
        gemm_phase<16>(g_hc, Wm, bm, g_gl, Bn, Hn, HCn, sA, sW);
        gbar(barcnt);

        // ---- P4: qg = gl @ Wq_g^T + bq_g ----
        gemm_phase<16>(g_gl, Wq_g, bq_g, g_qg, Bn, Hn, Hn, sA, sW);
        gbar(barcnt);

        // ---- P5: attention g (scores + softmax + weighted sum) ----
        for (int b = blockIdx.x; b < Bn; b += gridDim.x) {
            __syncthreads();
            const float4* src = (const float4*)(g_eg + (size_t)b * Ln * Hn);
            float4* d4 = (float4*)es;
            #pragma unroll
            for (int i = t; i < 4096; i += 256) d4[i] = src[i];
            qs[t] = g_qg[b*Hn + t];
            vs[t] = v_g[t];
            __syncthreads();

            #pragma unroll
            for (int l0 = 0; l0 < 64; l0 += 8) {
                int l = l0 + warp;
                const float* row = es + l * 256;
                float acc = 0.f;
                #pragma unroll
                for (int j = 0; j < 8; j++) {
                    int h = lane + 32*j;
                    acc += vs[h] * tanhf(qs[h] + row[h]);
                }
                #pragma unroll
                for (int o = 16; o; o >>= 1) acc += __shfl_xor_sync(0xffffffffu, acc, o);
                if (lane == 0) wv[l] = g_mask[b*Ln + l] ? NEGV : acc;
            }
            __syncthreads();

            if (warp == 0) {
                float a = wv[lane], c = wv[lane + 32];
                float m = fmaxf(a, c);
                #pragma unroll
                for (int o = 16; o; o >>= 1) m = fmaxf(m, __shfl_xor_sync(0xffffffffu, m, o));
                float ea = expf(a - m), ec = expf(c - m);
                float s = ea + ec;
                #pragma unroll
                for (int o = 16; o; o >>= 1) s += __shfl_xor_sync(0xffffffffu, s, o);
                wv[lane]      = ea / s;
                wv[lane + 32] = ec / s;
            }
            __syncthreads();

            float acc = 0.f;
            #pragma unroll
            for (int l = 0; l < 64; l++) acc += es[l*256 + t] * wv[l];
            g_gl2[b*Hn + t] = acc;
        }
        gbar(barcnt);

        // ---- P6: qp = gl2 @ Wq_p^T + bq_p ----
        gemm_phase<16>(g_gl2, Wq_p, bq_p, g_qp, Bn, Hn, Hn, sA, sW);
        gbar(barcnt);

        // ---- P7: attention p (log-softmax + argmax + mask + gather) ----
        for (int b = blockIdx.x; b < Bn; b += gridDim.x) {
            __syncthreads();
            const float4* src = (const float4*)(g_ep + (size_t)b * Ln * Hn);
            float4* d4 = (float4*)es;
            #pragma unroll
            for (int i = t; i < 4096; i += 256) d4[i] = src[i];
            qs[t] = g_qp[b*Hn + t];
            vs[t] = v_p[t];
            __syncthreads();

            #pragma unroll
            for (int l0 = 0; l0 < 64; l0 += 8) {
                int l = l0 + warp;
                const float* row = es + l * 256;
                float acc = 0.f;
                #pragma unroll
                for (int j = 0; j < 8; j++) {
                    int h = lane + 32*j;
                    acc += vs[h] * tanhf(qs[h] + row[h]);
                }
                #pragma unroll
                for (int o = 16; o; o >>= 1) acc += __shfl_xor_sync(0xffffffffu, acc, o);
                if (lane == 0) wv[l] = g_mask[b*Ln + l] ? NEGV : (10.0f * tanhf(acc));
            }
            __syncthreads();

            if (warp == 0) {
                float a = wv[lane], c = wv[lane + 32];
                float m = fmaxf(a, c);
                #pragma unroll
                for (int o = 16; o; o >>= 1) m = fmaxf(m, __shfl_xor_sync(0xffffffffu, m, o));
                float s = expf(a - m) + expf(c - m);
                #pragma unroll
                for (int o = 16; o; o >>= 1) s += __shfl_xor_sync(0xffffffffu, s, o);
                float bv = a; int bi = lane;
                if (c > bv) { bv = c; bi = lane + 32; }
                #pragma unroll
                for (int o = 16; o; o >>= 1) {
                    float ov = __shfl_xor_sync(0xffffffffu, bv, o);
                    int   oi = __shfl_xor_sync(0xffffffffu, bi, o);
                    if (ov > bv || (ov == bv && oi < bi)) { bv = ov; bi = oi; }
                }
                if (lane == 0) {
                    s_m = m; s_ls = logf(s); s_sel = bi;
                    unsigned char* mk = g_mask + b*Ln;
                    mk[bi] = 1;
                    int cnt = 0;
                    #pragma unroll
                    for (int l = 0; l < Ln; l++) cnt += mk[l];
                    if (cnt == Ln) mk[Ln - 1] = 0;
                    out[(size_t)(Bn*Ln*Ln) + (size_t)b*Ln + step] = (float)bi;
                }
            }
            __syncthreads();

            if (t < Ln)
                out[(size_t)b*Ln*Ln + (size_t)step*Ln + t] = wv[t] - s_m - s_ls;

            int sel = s_sel;
            g_xh[b*KX + t] = emb[((size_t)sel*Bn + b)*En + t];
        }
        gbar(barcnt);
    }
}

// ---------------- host ----------------
extern "C" void kernel_launch(void* const* d_in, const int* in_sizes, int n_in,
                              void* d_out, int out_size)
{
    const float* dec     = (const float*)d_in[0];
    const float* emb     = (const float*)d_in[1];
    const float* h0      = (const float*)d_in[2];
    const float* c0      = (const float*)d_in[3];
    const float* ctx     = (const float*)d_in[4];
    const float* courier = (const float*)d_in[5];
    const unsigned char* initm = (const unsigned char*)d_in[6];
    const float* W_ih = (const float*)d_in[7];
    const float* W_hh = (const float*)d_in[8];
    const float* b_ih = (const float*)d_in[9];
    const float* b_hh = (const float*)d_in[10];
    const float* Wm   = (const float*)d_in[11];
    const float* bm   = (const float*)d_in[12];
    const float* Wq_p = (const float*)d_in[13];
    const float* bq_p = (const float*)d_in[14];
    const float* Wr_p = (const float*)d_in[15];
    const float* br_p = (const float*)d_in[16];
    const float* v_p  = (const float*)d_in[17];
    const float* Wq_g = (const float*)d_in[18];
    const float* bq_g = (const float*)d_in[19];
    const float* Wr_g = (const float*)d_in[20];
    const float* br_g = (const float*)d_in[21];
    const float* v_g  = (const float*)d_in[22];
    float* out = (float*)d_out;

    cudaFuncSetAttribute(persist_kernel, cudaFuncAttributeMaxDynamicSharedMemorySize, 65536);

    float *eg, *ep;
    cudaGetSymbolAddress((void**)&eg, g_eg);
    cudaGetSymbolAddress((void**)&ep, g_ep);

    setup_kernel<<<1024, 512>>>(dec, h0, c0, courier, initm, W_ih, W_hh, b_ih, b_hh);

    // e_g / e_p = context @ Wr^T + br, stored [b][l][h]
    gemm_bias<1><<<dim3(Hn/64, (Bn*Ln)/64), 256>>>(ctx, Wr_g, br_g, eg, Bn*Ln, Hn, Hn);
    gemm_bias<1><<<dim3(Hn/64, (Bn*Ln)/64), 256>>>(ctx, Wr_p, br_p, ep, Bn*Ln, Hn, Hn);

    persist_kernel<<<NBLK, 256, 65536>>>(emb, Wm, bm, Wq_g, bq_g, Wq_p, bq_p,
                                         v_g, v_p, out);
}